// round 14
// baseline (speedup 1.0000x reference)
#include <cuda_runtime.h>
#include <cuda_bf16.h>
#include <cstdint>
#include <math.h>

#define NE   8
#define DM   768
#define HM   3072
#define NTOK 4096
#define CAP  2048

#define BM 128
#define BN 128
#define BK 32
#define KSTRIDE 40                 // padded SMEM row stride in bf16 elems (80B)
#define TILE_B   (BM * KSTRIDE * 2)        // 10240 bytes per tile
#define STAGE_B  (4 * TILE_B)              // Ah, Al, Bh, Bl  (37888 B)
#define NSTAGE 3
#define SMEM_BYTES (NSTAGE * STAGE_B)      // 113664 B; x2 CTAs = 227.3KB <= 228KB

using bf16 = __nv_bfloat16;

// ---------------- device scratch ----------------
__device__ int   g_count[NE];
__device__ int   g_rows[NE * CAP];
__device__ int   g_slot_e[NTOK * 2];
__device__ int   g_slot_p[NTOK * 2];
__device__ float g_score[NTOK * 2];

__device__ __align__(16) bf16  g_xh[NTOK * DM];
__device__ __align__(16) bf16  g_xl[NTOK * DM];
__device__ __align__(16) bf16  g_w1h[(size_t)NE * HM * DM];   // transposed: [e][h][d]
__device__ __align__(16) bf16  g_w1l[(size_t)NE * HM * DM];
__device__ __align__(16) bf16  g_w2h[(size_t)NE * DM * HM];   // transposed: [e][d][h]
__device__ __align__(16) bf16  g_w2l[(size_t)NE * DM * HM];
__device__ __align__(16) bf16  g_Hh[(size_t)NE * CAP * HM];
__device__ __align__(16) bf16  g_Hl[(size_t)NE * CAP * HM];
__device__ __align__(16) float g_Y[(size_t)NE * CAP * DM];

// ---------------- helpers ----------------
__device__ __forceinline__ uint32_t smem_u32(const void* p) {
    uint32_t a;
    asm("{ .reg .u64 t; cvta.to.shared.u64 t, %1; cvt.u32.u64 %0, t; }" : "=r"(a) : "l"(p));
    return a;
}
__device__ __forceinline__ void cp16(uint32_t dst, const void* src, int szbytes) {
    asm volatile("cp.async.cg.shared.global [%0], [%1], 16, %2;"
                 :: "r"(dst), "l"(src), "r"(szbytes) : "memory");
}
#define CP_COMMIT asm volatile("cp.async.commit_group;" ::: "memory")
#define CP_WAIT1  asm volatile("cp.async.wait_group 1;" ::: "memory")

#define LDSM4(r0, r1, r2, r3, addr)                                              \
    asm volatile("ldmatrix.sync.aligned.m8n8.x4.shared.b16 {%0,%1,%2,%3}, [%4];" \
                 : "=r"(r0), "=r"(r1), "=r"(r2), "=r"(r3) : "r"(addr))

__device__ __forceinline__ void mma16816(float* c,
                                         uint32_t a0, uint32_t a1, uint32_t a2, uint32_t a3,
                                         uint32_t b0, uint32_t b1) {
    asm volatile(
        "mma.sync.aligned.m16n8k16.row.col.f32.bf16.bf16.f32 "
        "{%0,%1,%2,%3}, {%4,%5,%6,%7}, {%8,%9}, {%0,%1,%2,%3};"
        : "+f"(c[0]), "+f"(c[1]), "+f"(c[2]), "+f"(c[3])
        : "r"(a0), "r"(a1), "r"(a2), "r"(a3), "r"(b0), "r"(b1));
}

__device__ __forceinline__ void split2(float v, bf16& h, bf16& l) {
    h = __float2bfloat16_rn(v);
    l = __float2bfloat16_rn(v - __bfloat162float(h));
}
__device__ __forceinline__ uint32_t pack_bf(bf16 a, bf16 b) {
    unsigned short ua = *(unsigned short*)&a, ub = *(unsigned short*)&b;
    return (uint32_t)ua | ((uint32_t)ub << 16);
}
__device__ __forceinline__ float gelu_tanh(float v) {
    float u = 0.7978845608028654f * (v + 0.044715f * v * v * v);
    return 0.5f * v * (1.f + tanhf(u));
}

// one BK=32 stage of the 3-pass split MMA  (verified path: B N-major, non-trans LDSM)
__device__ __forceinline__ void tile_compute(uint32_t As, int lane, int wm, int wn,
                                             float acc[4][4][4]) {
    const uint32_t Alo = As + TILE_B, Bhi = As + 2 * TILE_B, Blo = As + 3 * TILE_B;
#pragma unroll
    for (int ks = 0; ks < 2; ++ks) {
        uint32_t ah[16], bh[8], bl[8], al[16];
        const int arow = lane & 15, acol = ks * 16 + ((lane >> 4) << 3);
        const int brow = (lane & 7) + (((lane >> 4) & 1) << 3);
        const int bcol = ks * 16 + (((lane >> 3) & 1) << 3);
#pragma unroll
        for (int i = 0; i < 4; ++i) {
            uint32_t a = As + (uint32_t)((wm + i * 16 + arow) * KSTRIDE + acol) * 2;
            LDSM4(ah[4 * i], ah[4 * i + 1], ah[4 * i + 2], ah[4 * i + 3], a);
        }
#pragma unroll
        for (int p = 0; p < 2; ++p) {
            uint32_t a = Bhi + (uint32_t)((wn + p * 16 + brow) * KSTRIDE + bcol) * 2;
            LDSM4(bh[4 * p], bh[4 * p + 1], bh[4 * p + 2], bh[4 * p + 3], a);
        }
#pragma unroll
        for (int i = 0; i < 4; ++i)
#pragma unroll
            for (int j = 0; j < 4; ++j)
                mma16816(acc[i][j], ah[4 * i], ah[4 * i + 1], ah[4 * i + 2], ah[4 * i + 3],
                         bh[(j >> 1) * 4 + (j & 1) * 2], bh[(j >> 1) * 4 + (j & 1) * 2 + 1]);
#pragma unroll
        for (int p = 0; p < 2; ++p) {
            uint32_t a = Blo + (uint32_t)((wn + p * 16 + brow) * KSTRIDE + bcol) * 2;
            LDSM4(bl[4 * p], bl[4 * p + 1], bl[4 * p + 2], bl[4 * p + 3], a);
        }
#pragma unroll
        for (int i = 0; i < 4; ++i)
#pragma unroll
            for (int j = 0; j < 4; ++j)
                mma16816(acc[i][j], ah[4 * i], ah[4 * i + 1], ah[4 * i + 2], ah[4 * i + 3],
                         bl[(j >> 1) * 4 + (j & 1) * 2], bl[(j >> 1) * 4 + (j & 1) * 2 + 1]);
#pragma unroll
        for (int i = 0; i < 4; ++i) {
            uint32_t a = Alo + (uint32_t)((wm + i * 16 + arow) * KSTRIDE + acol) * 2;
            LDSM4(al[4 * i], al[4 * i + 1], al[4 * i + 2], al[4 * i + 3], a);
        }
#pragma unroll
        for (int i = 0; i < 4; ++i)
#pragma unroll
            for (int j = 0; j < 4; ++j)
                mma16816(acc[i][j], al[4 * i], al[4 * i + 1], al[4 * i + 2], al[4 * i + 3],
                         bh[(j >> 1) * 4 + (j & 1) * 2], bh[(j >> 1) * 4 + (j & 1) * 2 + 1]);
    }
}

// ---------------- control kernels ----------------
__global__ void zero_kernel() {
    if (threadIdx.x < NE) g_count[threadIdx.x] = 0;
}

__global__ void gate_kernel(const float* __restrict__ inp,
                            const float* __restrict__ gw,
                            const float* __restrict__ gb) {
    int n = blockIdx.x, tid = threadIdx.x;
    float acc[NE];
#pragma unroll
    for (int e = 0; e < NE; e++) acc[e] = 0.f;
    const float* x = inp + (size_t)n * DM;
    for (int d = tid; d < DM; d += 256) {
        float xv = x[d];
#pragma unroll
        for (int e = 0; e < NE; e++) acc[e] += xv * gw[d * NE + e];
    }
#pragma unroll
    for (int e = 0; e < NE; e++)
#pragma unroll
        for (int off = 16; off > 0; off >>= 1)
            acc[e] += __shfl_down_sync(0xffffffffu, acc[e], off);
    __shared__ float sred[8][NE];
    int warp = tid >> 5, lane = tid & 31;
    if (lane == 0)
#pragma unroll
        for (int e = 0; e < NE; e++) sred[warp][e] = acc[e];
    __syncthreads();
    if (tid == 0) {
        float logits[NE];
#pragma unroll
        for (int e = 0; e < NE; e++) {
            float s = gb[e];
#pragma unroll
            for (int w = 0; w < 8; w++) s += sred[w][e];
            logits[e] = s;
        }
        int i0 = 0;
#pragma unroll
        for (int e = 1; e < NE; e++) if (logits[e] > logits[i0]) i0 = e;
        int i1 = -1;
#pragma unroll
        for (int e = 0; e < NE; e++) {
            if (e == i0) continue;
            if (i1 < 0 || logits[e] > logits[i1]) i1 = e;
        }
        float v0 = logits[i0], v1 = logits[i1];
        float e1 = expf(v1 - v0);
        float inv = 1.f / (1.f + e1);
        int p0 = atomicAdd(&g_count[i0], 1);
        int p1 = atomicAdd(&g_count[i1], 1);
        if (p0 < CAP) g_rows[i0 * CAP + p0] = n; else p0 = -1;
        if (p1 < CAP) g_rows[i1 * CAP + p1] = n; else p1 = -1;
        g_slot_e[n * 2 + 0] = i0; g_slot_p[n * 2 + 0] = p0; g_score[n * 2 + 0] = inv;
        g_slot_e[n * 2 + 1] = i1; g_slot_p[n * 2 + 1] = p1; g_score[n * 2 + 1] = e1 * inv;
    }
}

// ---------------- streaming fp32 -> bf16 hi/lo split (X: no transpose) ----------------
__global__ void convert_x(const float* __restrict__ x) {
    int i4 = blockIdx.x * blockDim.x + threadIdx.x;
    if (i4 >= NTOK * DM / 4) return;
    float4 v = ((const float4*)x)[i4];
    bf16 h0, l0, h1, l1, h2, l2, h3, l3;
    split2(v.x, h0, l0); split2(v.y, h1, l1); split2(v.z, h2, l2); split2(v.w, h3, l3);
    ((uint2*)g_xh)[i4] = make_uint2(pack_bf(h0, h1), pack_bf(h2, h3));
    ((uint2*)g_xl)[i4] = make_uint2(pack_bf(l0, l1), pack_bf(l2, l3));
}

// ---------------- fast transpose + split: src [E][K][N] -> dst [E][N][K] ----------------
__device__ __forceinline__ void transpose_split_tile(const float* __restrict__ src,
                                                     bf16* __restrict__ dh,
                                                     bf16* __restrict__ dl,
                                                     int K, int N) {
    __shared__ float s[64][65];
    const int e = blockIdx.z, k0 = blockIdx.y * 64, n0 = blockIdx.x * 64;
    const int tid = threadIdx.x;
    const float* sp = src + ((size_t)e * K + k0) * N + n0;
#pragma unroll
    for (int l = 0; l < 4; ++l) {
        int idx = tid + l * 256;
        int r = idx >> 4, c = (idx & 15) * 4;
        float4 v = *(const float4*)(sp + (size_t)r * N + c);
        s[r][c + 0] = v.x; s[r][c + 1] = v.y; s[r][c + 2] = v.z; s[r][c + 3] = v.w;
    }
    __syncthreads();
    bf16* dhp = dh + ((size_t)e * N + n0) * K + k0;
    bf16* dlp = dl + ((size_t)e * N + n0) * K + k0;
#pragma unroll
    for (int l = 0; l < 2; ++l) {
        int idx = tid + l * 256;
        int r = idx >> 3, c8 = (idx & 7) * 8;      // r = n-row, c8 = k-offset
        bf16 h[8], lo[8];
#pragma unroll
        for (int q = 0; q < 8; ++q) split2(s[c8 + q][r], h[q], lo[q]);
        uint4 hv = make_uint4(pack_bf(h[0], h[1]), pack_bf(h[2], h[3]),
                              pack_bf(h[4], h[5]), pack_bf(h[6], h[7]));
        uint4 lv = make_uint4(pack_bf(lo[0], lo[1]), pack_bf(lo[2], lo[3]),
                              pack_bf(lo[4], lo[5]), pack_bf(lo[6], lo[7]));
        *(uint4*)(dhp + (size_t)r * K + c8) = hv;
        *(uint4*)(dlp + (size_t)r * K + c8) = lv;
    }
}
__global__ void __launch_bounds__(256) convert_w1_fast(const float* __restrict__ w) {
    transpose_split_tile(w, g_w1h, g_w1l, DM, HM);   // [e][DM][HM] -> [e][HM][DM]
}
__global__ void __launch_bounds__(256) convert_w2_fast(const float* __restrict__ w) {
    transpose_split_tile(w, g_w2h, g_w2l, HM, DM);   // [e][HM][DM] -> [e][DM][HM]
}

// ---------------- GEMM1 ----------------
__global__ void __launch_bounds__(256, 2) gemm1_mma(const float* __restrict__ b1) {
    extern __shared__ char smem[];
    const int tid = threadIdx.x, wid = tid >> 5, lane = tid & 31;
    const int e = blockIdx.z, m0 = blockIdx.x * BM, n0 = blockIdx.y * BN;
    const int cnt = min(g_count[e], CAP);
    if (m0 >= cnt) return;

    __shared__ int rowTok[BM];
    if (tid < BM) rowTok[tid] = (m0 + tid < cnt) ? g_rows[e * CAP + m0 + tid] : -1;
    __syncthreads();

    const uint32_t sbase = smem_u32(smem);
    const int wm = (wid & 1) * 64, wn = (wid >> 1) * 32;

    float acc[4][4][4];
#pragma unroll
    for (int i = 0; i < 4; ++i)
#pragma unroll
        for (int j = 0; j < 4; ++j)
#pragma unroll
            for (int q = 0; q < 4; ++q) acc[i][j][q] = 0.f;

    auto load_stage = [&](int stage, int k0) {
        uint32_t st = sbase + stage * STAGE_B;
#pragma unroll
        for (int l = 0; l < 2; ++l) {
            int idx = tid + l * 256;
            int r = idx >> 2, c = idx & 3;
            uint32_t doff = (uint32_t)(r * KSTRIDE + c * 8) * 2;
            int tok = rowTok[r];
            size_t aoff = (size_t)max(tok, 0) * DM + k0 + c * 8;
            int sz = tok >= 0 ? 16 : 0;
            cp16(st + doff, g_xh + aoff, sz);
            cp16(st + TILE_B + doff, g_xl + aoff, sz);
            size_t brow = ((size_t)e * HM + n0 + r) * DM + k0 + c * 8;
            cp16(st + 2 * TILE_B + doff, g_w1h + brow, 16);
            cp16(st + 3 * TILE_B + doff, g_w1l + brow, 16);
        }
    };

    const int KT = DM / BK;
    load_stage(0, 0);
    CP_COMMIT;
    load_stage(1, BK);
    CP_COMMIT;
    int cur = 0, nxt = 2;
#pragma unroll 1
    for (int kt = 0; kt < KT; ++kt) {
        CP_WAIT1;
        __syncthreads();
        tile_compute(sbase + cur * STAGE_B, lane, wm, wn, acc);
        if (kt + 2 < KT) load_stage(nxt, (kt + 2) * BK);
        CP_COMMIT;
        cur = (cur == 2) ? 0 : cur + 1;
        nxt = (nxt == 2) ? 0 : nxt + 1;
    }

    const float* b1e = b1 + (size_t)e * HM;
#pragma unroll
    for (int i = 0; i < 4; ++i) {
        int rbase = m0 + wm + i * 16 + (lane >> 2);
#pragma unroll
        for (int h = 0; h < 2; ++h) {
            int r = rbase + h * 8;
            if (r >= cnt) continue;
            size_t rowoff = ((size_t)e * CAP + r) * HM;
#pragma unroll
            for (int j = 0; j < 4; ++j) {
                int col = n0 + wn + j * 8 + (lane & 3) * 2;
                float v0 = gelu_tanh(acc[i][j][h * 2 + 0] + b1e[col]);
                float v1 = gelu_tanh(acc[i][j][h * 2 + 1] + b1e[col + 1]);
                bf16 h0, l0, h1, l1;
                split2(v0, h0, l0); split2(v1, h1, l1);
                *(uint32_t*)(g_Hh + rowoff + col) = pack_bf(h0, h1);
                *(uint32_t*)(g_Hl + rowoff + col) = pack_bf(l0, l1);
            }
        }
    }
}

// ---------------- GEMM2 ----------------
__global__ void __launch_bounds__(256, 2) gemm2_mma(const float* __restrict__ b2) {
    extern __shared__ char smem[];
    const int tid = threadIdx.x, wid = tid >> 5, lane = tid & 31;
    const int e = blockIdx.z, m0 = blockIdx.x * BM, n0 = blockIdx.y * BN;
    const int cnt = min(g_count[e], CAP);
    if (m0 >= cnt) return;

    const uint32_t sbase = smem_u32(smem);
    const int wm = (wid & 1) * 64, wn = (wid >> 1) * 32;

    float acc[4][4][4];
#pragma unroll
    for (int i = 0; i < 4; ++i)
#pragma unroll
        for (int j = 0; j < 4; ++j)
#pragma unroll
            for (int q = 0; q < 4; ++q) acc[i][j][q] = 0.f;

    auto load_stage = [&](int stage, int k0) {
        uint32_t st = sbase + stage * STAGE_B;
#pragma unroll
        for (int l = 0; l < 2; ++l) {
            int idx = tid + l * 256;
            int r = idx >> 2, c = idx & 3;
            uint32_t doff = (uint32_t)(r * KSTRIDE + c * 8) * 2;
            int mrow = m0 + r;
            int sz = mrow < cnt ? 16 : 0;
            size_t aoff = ((size_t)e * CAP + mrow) * HM + k0 + c * 8;
            cp16(st + doff, g_Hh + aoff, sz);
            cp16(st + TILE_B + doff, g_Hl + aoff, sz);
            size_t brow = ((size_t)e * DM + n0 + r) * HM + k0 + c * 8;
            cp16(st + 2 * TILE_B + doff, g_w2h + brow, 16);
            cp16(st + 3 * TILE_B + doff, g_w2l + brow, 16);
        }
    };

    const int KT = HM / BK;
    load_stage(0, 0);
    CP_COMMIT;
    load_stage(1, BK);
    CP_COMMIT;
    int cur = 0, nxt = 2;
#pragma unroll 1
    for (int kt = 0; kt < KT; ++kt) {
        CP_WAIT1;
        __syncthreads();
        tile_compute(sbase + cur * STAGE_B, lane, wm, wn, acc);
        if (kt + 2 < KT) load_stage(nxt, (kt + 2) * BK);
        CP_COMMIT;
        cur = (cur == 2) ? 0 : cur + 1;
        nxt = (nxt == 2) ? 0 : nxt + 1;
    }

    const float* b2e = b2 + (size_t)e * DM;
#pragma unroll
    for (int i = 0; i < 4; ++i) {
        int rbase = m0 + wm + i * 16 + (lane >> 2);
#pragma unroll
        for (int h = 0; h < 2; ++h) {
            int r = rbase + h * 8;
            if (r >= cnt) continue;
            size_t rowoff = ((size_t)e * CAP + r) * DM;
#pragma unroll
            for (int j = 0; j < 4; ++j) {
                int col = n0 + wn + j * 8 + (lane & 3) * 2;
                float2 o;
                o.x = acc[i][j][h * 2 + 0] + b2e[col];
                o.y = acc[i][j][h * 2 + 1] + b2e[col + 1];
                *(float2*)(g_Y + rowoff + col) = o;
            }
        }
    }
}

// ---------------- combine ----------------
__global__ void combine_kernel(float* __restrict__ out) {
    int idx = blockIdx.x * blockDim.x + threadIdx.x;
    if (idx >= NTOK * (DM / 4)) return;
    int n = idx / (DM / 4), d4 = idx % (DM / 4);
    int   e0 = g_slot_e[n * 2 + 0], p0 = g_slot_p[n * 2 + 0];
    int   e1 = g_slot_e[n * 2 + 1], p1 = g_slot_p[n * 2 + 1];
    float s0 = g_score[n * 2 + 0],  s1 = g_score[n * 2 + 1];
    float4 r = make_float4(0.f, 0.f, 0.f, 0.f);
    if (p0 >= 0) {
        float4 y = *(const float4*)&g_Y[((size_t)e0 * CAP + p0) * DM + d4 * 4];
        r.x += s0 * y.x; r.y += s0 * y.y; r.z += s0 * y.z; r.w += s0 * y.w;
    }
    if (p1 >= 0) {
        float4 y = *(const float4*)&g_Y[((size_t)e1 * CAP + p1) * DM + d4 * 4];
        r.x += s1 * y.x; r.y += s1 * y.y; r.z += s1 * y.z; r.w += s1 * y.w;
    }
    *(float4*)&out[(size_t)n * DM + d4 * 4] = r;
}

// ---------------- launch ----------------
extern "C" void kernel_launch(void* const* d_in, const int* in_sizes, int n_in,
                              void* d_out, int out_size) {
    const float* inp = (const float*)d_in[0];
    const float* gw  = (const float*)d_in[1];
    const float* gb  = (const float*)d_in[2];
    const float* w1  = (const float*)d_in[3];
    const float* b1  = (const float*)d_in[4];
    const float* w2  = (const float*)d_in[5];
    const float* b2  = (const float*)d_in[6];
    float* out = (float*)d_out;

    cudaFuncSetAttribute(gemm1_mma, cudaFuncAttributeMaxDynamicSharedMemorySize, SMEM_BYTES);
    cudaFuncSetAttribute(gemm2_mma, cudaFuncAttributeMaxDynamicSharedMemorySize, SMEM_BYTES);

    zero_kernel<<<1, 32>>>();
    gate_kernel<<<NTOK, 256>>>(inp, gw, gb);
    convert_x<<<(NTOK * DM / 4 + 255) / 256, 256>>>(inp);
    convert_w1_fast<<<dim3(HM / 64, DM / 64, NE), 256>>>(w1);
    convert_w2_fast<<<dim3(DM / 64, HM / 64, NE), 256>>>(w2);
    gemm1_mma<<<dim3(CAP / BM, HM / BN, NE), 256, SMEM_BYTES>>>(b1);
    gemm2_mma<<<dim3(CAP / BM, DM / BN, NE), 256, SMEM_BYTES>>>(b2);
    combine_kernel<<<(NTOK * (DM / 4) + 255) / 256, 256>>>(out);
}

// round 16
// speedup vs baseline: 1.0685x; 1.0685x over previous
#include <cuda_runtime.h>
#include <cuda_bf16.h>
#include <cstdint>
#include <math.h>

#define NE   8
#define DM   768
#define HM   3072
#define NTOK 4096
#define CAP  2048

#define BM 128
#define BN 128
#define BK 32
#define KSTRIDE 40                 // padded SMEM row stride in bf16 elems (80B)
#define TILE_B   (BM * KSTRIDE * 2)        // 10240 bytes per tile
#define STAGE_B  (4 * TILE_B)              // Ah, Al, Bh, Bl
#define SMEM_BYTES (2 * STAGE_B)           // 75776 -> 2 CTAs/SM fits easily

using bf16 = __nv_bfloat16;

// ---------------- device scratch ----------------
__device__ int   g_count[NE];
__device__ int   g_rows[NE * CAP];
__device__ int   g_slot_e[NTOK * 2];
__device__ int   g_slot_p[NTOK * 2];
__device__ float g_score[NTOK * 2];

__device__ __align__(16) bf16  g_xh[NTOK * DM];
__device__ __align__(16) bf16  g_xl[NTOK * DM];
__device__ __align__(16) bf16  g_w1h[(size_t)NE * HM * DM];   // transposed: [e][h][d]
__device__ __align__(16) bf16  g_w1l[(size_t)NE * HM * DM];
__device__ __align__(16) bf16  g_w2h[(size_t)NE * DM * HM];   // transposed: [e][d][h]
__device__ __align__(16) bf16  g_w2l[(size_t)NE * DM * HM];
__device__ __align__(16) bf16  g_Hh[(size_t)NE * CAP * HM];
__device__ __align__(16) bf16  g_Hl[(size_t)NE * CAP * HM];
__device__ __align__(16) float g_Y[(size_t)NE * CAP * DM];

// ---------------- helpers ----------------
__device__ __forceinline__ uint32_t smem_u32(const void* p) {
    uint32_t a;
    asm("{ .reg .u64 t; cvta.to.shared.u64 t, %1; cvt.u32.u64 %0, t; }" : "=r"(a) : "l"(p));
    return a;
}
__device__ __forceinline__ void cp16(uint32_t dst, const void* src, int szbytes) {
    asm volatile("cp.async.cg.shared.global [%0], [%1], 16, %2;"
                 :: "r"(dst), "l"(src), "r"(szbytes) : "memory");
}
#define CP_COMMIT asm volatile("cp.async.commit_group;" ::: "memory")
#define CP_WAIT0  asm volatile("cp.async.wait_group 0;" ::: "memory")

#define LDSM4(r0, r1, r2, r3, addr)                                              \
    asm volatile("ldmatrix.sync.aligned.m8n8.x4.shared.b16 {%0,%1,%2,%3}, [%4];" \
                 : "=r"(r0), "=r"(r1), "=r"(r2), "=r"(r3) : "r"(addr))

__device__ __forceinline__ void mma16816(float* c,
                                         uint32_t a0, uint32_t a1, uint32_t a2, uint32_t a3,
                                         uint32_t b0, uint32_t b1) {
    asm volatile(
        "mma.sync.aligned.m16n8k16.row.col.f32.bf16.bf16.f32 "
        "{%0,%1,%2,%3}, {%4,%5,%6,%7}, {%8,%9}, {%0,%1,%2,%3};"
        : "+f"(c[0]), "+f"(c[1]), "+f"(c[2]), "+f"(c[3])
        : "r"(a0), "r"(a1), "r"(a2), "r"(a3), "r"(b0), "r"(b1));
}

__device__ __forceinline__ void split2(float v, bf16& h, bf16& l) {
    h = __float2bfloat16_rn(v);
    l = __float2bfloat16_rn(v - __bfloat162float(h));
}
__device__ __forceinline__ uint32_t pack_bf(bf16 a, bf16 b) {
    unsigned short ua = *(unsigned short*)&a, ub = *(unsigned short*)&b;
    return (uint32_t)ua | ((uint32_t)ub << 16);
}
__device__ __forceinline__ float gelu_tanh(float v) {
    float u = 0.7978845608028654f * (v + 0.044715f * v * v * v);
    return 0.5f * v * (1.f + tanhf(u));
}

// one BK=32 stage of the 3-pass split MMA  (verified path: B N-major, non-trans LDSM)
__device__ __forceinline__ void tile_compute(uint32_t As, int lane, int wm, int wn,
                                             float acc[4][4][4]) {
    const uint32_t Alo = As + TILE_B, Bhi = As + 2 * TILE_B, Blo = As + 3 * TILE_B;
#pragma unroll
    for (int ks = 0; ks < 2; ++ks) {
        uint32_t ah[16], bh[8], bl[8], al[16];
        const int arow = lane & 15, acol = ks * 16 + ((lane >> 4) << 3);
        const int brow = (lane & 7) + (((lane >> 4) & 1) << 3);
        const int bcol = ks * 16 + (((lane >> 3) & 1) << 3);
#pragma unroll
        for (int i = 0; i < 4; ++i) {
            uint32_t a = As + (uint32_t)((wm + i * 16 + arow) * KSTRIDE + acol) * 2;
            LDSM4(ah[4 * i], ah[4 * i + 1], ah[4 * i + 2], ah[4 * i + 3], a);
        }
#pragma unroll
        for (int p = 0; p < 2; ++p) {
            uint32_t a = Bhi + (uint32_t)((wn + p * 16 + brow) * KSTRIDE + bcol) * 2;
            LDSM4(bh[4 * p], bh[4 * p + 1], bh[4 * p + 2], bh[4 * p + 3], a);
        }
#pragma unroll
        for (int i = 0; i < 4; ++i)
#pragma unroll
            for (int j = 0; j < 4; ++j)
                mma16816(acc[i][j], ah[4 * i], ah[4 * i + 1], ah[4 * i + 2], ah[4 * i + 3],
                         bh[(j >> 1) * 4 + (j & 1) * 2], bh[(j >> 1) * 4 + (j & 1) * 2 + 1]);
#pragma unroll
        for (int p = 0; p < 2; ++p) {
            uint32_t a = Blo + (uint32_t)((wn + p * 16 + brow) * KSTRIDE + bcol) * 2;
            LDSM4(bl[4 * p], bl[4 * p + 1], bl[4 * p + 2], bl[4 * p + 3], a);
        }
#pragma unroll
        for (int i = 0; i < 4; ++i)
#pragma unroll
            for (int j = 0; j < 4; ++j)
                mma16816(acc[i][j], ah[4 * i], ah[4 * i + 1], ah[4 * i + 2], ah[4 * i + 3],
                         bl[(j >> 1) * 4 + (j & 1) * 2], bl[(j >> 1) * 4 + (j & 1) * 2 + 1]);
#pragma unroll
        for (int i = 0; i < 4; ++i) {
            uint32_t a = Alo + (uint32_t)((wm + i * 16 + arow) * KSTRIDE + acol) * 2;
            LDSM4(al[4 * i], al[4 * i + 1], al[4 * i + 2], al[4 * i + 3], a);
        }
#pragma unroll
        for (int i = 0; i < 4; ++i)
#pragma unroll
            for (int j = 0; j < 4; ++j)
                mma16816(acc[i][j], al[4 * i], al[4 * i + 1], al[4 * i + 2], al[4 * i + 3],
                         bh[(j >> 1) * 4 + (j & 1) * 2], bh[(j >> 1) * 4 + (j & 1) * 2 + 1]);
    }
}

// ---------------- control kernels ----------------
__global__ void zero_kernel() {
    if (threadIdx.x < NE) g_count[threadIdx.x] = 0;
}

__global__ void gate_kernel(const float* __restrict__ inp,
                            const float* __restrict__ gw,
                            const float* __restrict__ gb) {
    int n = blockIdx.x, tid = threadIdx.x;
    float acc[NE];
#pragma unroll
    for (int e = 0; e < NE; e++) acc[e] = 0.f;
    const float* x = inp + (size_t)n * DM;
    for (int d = tid; d < DM; d += 256) {
        float xv = x[d];
#pragma unroll
        for (int e = 0; e < NE; e++) acc[e] += xv * gw[d * NE + e];
    }
#pragma unroll
    for (int e = 0; e < NE; e++)
#pragma unroll
        for (int off = 16; off > 0; off >>= 1)
            acc[e] += __shfl_down_sync(0xffffffffu, acc[e], off);
    __shared__ float sred[8][NE];
    int warp = tid >> 5, lane = tid & 31;
    if (lane == 0)
#pragma unroll
        for (int e = 0; e < NE; e++) sred[warp][e] = acc[e];
    __syncthreads();
    if (tid == 0) {
        float logits[NE];
#pragma unroll
        for (int e = 0; e < NE; e++) {
            float s = gb[e];
#pragma unroll
            for (int w = 0; w < 8; w++) s += sred[w][e];
            logits[e] = s;
        }
        int i0 = 0;
#pragma unroll
        for (int e = 1; e < NE; e++) if (logits[e] > logits[i0]) i0 = e;
        int i1 = -1;
#pragma unroll
        for (int e = 0; e < NE; e++) {
            if (e == i0) continue;
            if (i1 < 0 || logits[e] > logits[i1]) i1 = e;
        }
        float v0 = logits[i0], v1 = logits[i1];
        float e1 = expf(v1 - v0);
        float inv = 1.f / (1.f + e1);
        int p0 = atomicAdd(&g_count[i0], 1);
        int p1 = atomicAdd(&g_count[i1], 1);
        if (p0 < CAP) g_rows[i0 * CAP + p0] = n; else p0 = -1;
        if (p1 < CAP) g_rows[i1 * CAP + p1] = n; else p1 = -1;
        g_slot_e[n * 2 + 0] = i0; g_slot_p[n * 2 + 0] = p0; g_score[n * 2 + 0] = inv;
        g_slot_e[n * 2 + 1] = i1; g_slot_p[n * 2 + 1] = p1; g_score[n * 2 + 1] = e1 * inv;
    }
}

// ---------------- streaming fp32 -> bf16 hi/lo split (X: no transpose) ----------------
__global__ void convert_x(const float* __restrict__ x) {
    int i4 = blockIdx.x * blockDim.x + threadIdx.x;
    if (i4 >= NTOK * DM / 4) return;
    float4 v = ((const float4*)x)[i4];
    bf16 h0, l0, h1, l1, h2, l2, h3, l3;
    split2(v.x, h0, l0); split2(v.y, h1, l1); split2(v.z, h2, l2); split2(v.w, h3, l3);
    ((uint2*)g_xh)[i4] = make_uint2(pack_bf(h0, h1), pack_bf(h2, h3));
    ((uint2*)g_xl)[i4] = make_uint2(pack_bf(l0, l1), pack_bf(l2, l3));
}

// ---------------- fast transpose + split: src [E][K][N] -> dst [E][N][K] ----------------
__device__ __forceinline__ void transpose_split_tile(const float* __restrict__ src,
                                                     bf16* __restrict__ dh,
                                                     bf16* __restrict__ dl,
                                                     int K, int N) {
    __shared__ float s[64][65];
    const int e = blockIdx.z, k0 = blockIdx.y * 64, n0 = blockIdx.x * 64;
    const int tid = threadIdx.x;
    const float* sp = src + ((size_t)e * K + k0) * N + n0;
#pragma unroll
    for (int l = 0; l < 4; ++l) {
        int idx = tid + l * 256;
        int r = idx >> 4, c = (idx & 15) * 4;
        float4 v = *(const float4*)(sp + (size_t)r * N + c);
        s[r][c + 0] = v.x; s[r][c + 1] = v.y; s[r][c + 2] = v.z; s[r][c + 3] = v.w;
    }
    __syncthreads();
    bf16* dhp = dh + ((size_t)e * N + n0) * K + k0;
    bf16* dlp = dl + ((size_t)e * N + n0) * K + k0;
#pragma unroll
    for (int l = 0; l < 2; ++l) {
        int idx = tid + l * 256;
        int r = idx >> 3, c8 = (idx & 7) * 8;      // r = n-row, c8 = k-offset
        bf16 h[8], lo[8];
#pragma unroll
        for (int q = 0; q < 8; ++q) split2(s[c8 + q][r], h[q], lo[q]);
        uint4 hv = make_uint4(pack_bf(h[0], h[1]), pack_bf(h[2], h[3]),
                              pack_bf(h[4], h[5]), pack_bf(h[6], h[7]));
        uint4 lv = make_uint4(pack_bf(lo[0], lo[1]), pack_bf(lo[2], lo[3]),
                              pack_bf(lo[4], lo[5]), pack_bf(lo[6], lo[7]));
        *(uint4*)(dhp + (size_t)r * K + c8) = hv;
        *(uint4*)(dlp + (size_t)r * K + c8) = lv;
    }
}
__global__ void __launch_bounds__(256) convert_w1_fast(const float* __restrict__ w) {
    transpose_split_tile(w, g_w1h, g_w1l, DM, HM);   // [e][DM][HM] -> [e][HM][DM]
}
__global__ void __launch_bounds__(256) convert_w2_fast(const float* __restrict__ w) {
    transpose_split_tile(w, g_w2h, g_w2l, HM, DM);   // [e][HM][DM] -> [e][DM][HM]
}

// ---------------- GEMM1 ----------------
__global__ void __launch_bounds__(256, 2) gemm1_mma(const float* __restrict__ b1) {
    extern __shared__ char smem[];
    const int tid = threadIdx.x, wid = tid >> 5, lane = tid & 31;
    const int e = blockIdx.z, m0 = blockIdx.x * BM, n0 = blockIdx.y * BN;
    const int cnt = min(g_count[e], CAP);
    if (m0 >= cnt) return;

    __shared__ int rowTok[BM];
    if (tid < BM) rowTok[tid] = (m0 + tid < cnt) ? g_rows[e * CAP + m0 + tid] : -1;
    __syncthreads();

    const uint32_t sbase = smem_u32(smem);
    const int wm = (wid & 1) * 64, wn = (wid >> 1) * 32;

    float acc[4][4][4];
#pragma unroll
    for (int i = 0; i < 4; ++i)
#pragma unroll
        for (int j = 0; j < 4; ++j)
#pragma unroll
            for (int q = 0; q < 4; ++q) acc[i][j][q] = 0.f;

    auto load_stage = [&](int stage, int k0) {
        uint32_t st = sbase + stage * STAGE_B;
#pragma unroll
        for (int l = 0; l < 2; ++l) {
            int idx = tid + l * 256;
            int r = idx >> 2, c = idx & 3;
            uint32_t doff = (uint32_t)(r * KSTRIDE + c * 8) * 2;
            int tok = rowTok[r];
            size_t aoff = (size_t)max(tok, 0) * DM + k0 + c * 8;
            int sz = tok >= 0 ? 16 : 0;
            cp16(st + doff, g_xh + aoff, sz);
            cp16(st + TILE_B + doff, g_xl + aoff, sz);
            size_t brow = ((size_t)e * HM + n0 + r) * DM + k0 + c * 8;
            cp16(st + 2 * TILE_B + doff, g_w1h + brow, 16);
            cp16(st + 3 * TILE_B + doff, g_w1l + brow, 16);
        }
    };

    const int KT = DM / BK;
    load_stage(0, 0);
    CP_COMMIT;
#pragma unroll 1
    for (int kt = 0; kt < KT; ++kt) {
        CP_WAIT0;                   // own copies for stage kt done
        __syncthreads();            // all warps' copies visible; prev compute done
        if (kt + 1 < KT) load_stage((kt + 1) & 1, (kt + 1) * BK);
        CP_COMMIT;
        tile_compute(sbase + (kt & 1) * STAGE_B, lane, wm, wn, acc);
    }

    const float* b1e = b1 + (size_t)e * HM;
#pragma unroll
    for (int i = 0; i < 4; ++i) {
        int rbase = m0 + wm + i * 16 + (lane >> 2);
#pragma unroll
        for (int h = 0; h < 2; ++h) {
            int r = rbase + h * 8;
            if (r >= cnt) continue;
            size_t rowoff = ((size_t)e * CAP + r) * HM;
#pragma unroll
            for (int j = 0; j < 4; ++j) {
                int col = n0 + wn + j * 8 + (lane & 3) * 2;
                float v0 = gelu_tanh(acc[i][j][h * 2 + 0] + b1e[col]);
                float v1 = gelu_tanh(acc[i][j][h * 2 + 1] + b1e[col + 1]);
                bf16 h0, l0, h1, l1;
                split2(v0, h0, l0); split2(v1, h1, l1);
                *(uint32_t*)(g_Hh + rowoff + col) = pack_bf(h0, h1);
                *(uint32_t*)(g_Hl + rowoff + col) = pack_bf(l0, l1);
            }
        }
    }
}

// ---------------- GEMM2 ----------------
__global__ void __launch_bounds__(256, 2) gemm2_mma(const float* __restrict__ b2) {
    extern __shared__ char smem[];
    const int tid = threadIdx.x, wid = tid >> 5, lane = tid & 31;
    const int e = blockIdx.z, m0 = blockIdx.x * BM, n0 = blockIdx.y * BN;
    const int cnt = min(g_count[e], CAP);
    if (m0 >= cnt) return;

    const uint32_t sbase = smem_u32(smem);
    const int wm = (wid & 1) * 64, wn = (wid >> 1) * 32;

    float acc[4][4][4];
#pragma unroll
    for (int i = 0; i < 4; ++i)
#pragma unroll
        for (int j = 0; j < 4; ++j)
#pragma unroll
            for (int q = 0; q < 4; ++q) acc[i][j][q] = 0.f;

    auto load_stage = [&](int stage, int k0) {
        uint32_t st = sbase + stage * STAGE_B;
#pragma unroll
        for (int l = 0; l < 2; ++l) {
            int idx = tid + l * 256;
            int r = idx >> 2, c = idx & 3;
            uint32_t doff = (uint32_t)(r * KSTRIDE + c * 8) * 2;
            int mrow = m0 + r;
            int sz = mrow < cnt ? 16 : 0;
            size_t aoff = ((size_t)e * CAP + mrow) * HM + k0 + c * 8;
            cp16(st + doff, g_Hh + aoff, sz);
            cp16(st + TILE_B + doff, g_Hl + aoff, sz);
            size_t brow = ((size_t)e * DM + n0 + r) * HM + k0 + c * 8;
            cp16(st + 2 * TILE_B + doff, g_w2h + brow, 16);
            cp16(st + 3 * TILE_B + doff, g_w2l + brow, 16);
        }
    };

    const int KT = HM / BK;
    load_stage(0, 0);
    CP_COMMIT;
#pragma unroll 1
    for (int kt = 0; kt < KT; ++kt) {
        CP_WAIT0;
        __syncthreads();
        if (kt + 1 < KT) load_stage((kt + 1) & 1, (kt + 1) * BK);
        CP_COMMIT;
        tile_compute(sbase + (kt & 1) * STAGE_B, lane, wm, wn, acc);
    }

    const float* b2e = b2 + (size_t)e * DM;
#pragma unroll
    for (int i = 0; i < 4; ++i) {
        int rbase = m0 + wm + i * 16 + (lane >> 2);
#pragma unroll
        for (int h = 0; h < 2; ++h) {
            int r = rbase + h * 8;
            if (r >= cnt) continue;
            size_t rowoff = ((size_t)e * CAP + r) * DM;
#pragma unroll
            for (int j = 0; j < 4; ++j) {
                int col = n0 + wn + j * 8 + (lane & 3) * 2;
                float2 o;
                o.x = acc[i][j][h * 2 + 0] + b2e[col];
                o.y = acc[i][j][h * 2 + 1] + b2e[col + 1];
                *(float2*)(g_Y + rowoff + col) = o;
            }
        }
    }
}

// ---------------- combine ----------------
__global__ void combine_kernel(float* __restrict__ out) {
    int idx = blockIdx.x * blockDim.x + threadIdx.x;
    if (idx >= NTOK * (DM / 4)) return;
    int n = idx / (DM / 4), d4 = idx % (DM / 4);
    int   e0 = g_slot_e[n * 2 + 0], p0 = g_slot_p[n * 2 + 0];
    int   e1 = g_slot_e[n * 2 + 1], p1 = g_slot_p[n * 2 + 1];
    float s0 = g_score[n * 2 + 0],  s1 = g_score[n * 2 + 1];
    float4 r = make_float4(0.f, 0.f, 0.f, 0.f);
    if (p0 >= 0) {
        float4 y = *(const float4*)&g_Y[((size_t)e0 * CAP + p0) * DM + d4 * 4];
        r.x += s0 * y.x; r.y += s0 * y.y; r.z += s0 * y.z; r.w += s0 * y.w;
    }
    if (p1 >= 0) {
        float4 y = *(const float4*)&g_Y[((size_t)e1 * CAP + p1) * DM + d4 * 4];
        r.x += s1 * y.x; r.y += s1 * y.y; r.z += s1 * y.z; r.w += s1 * y.w;
    }
    *(float4*)&out[(size_t)n * DM + d4 * 4] = r;
}

// ---------------- launch ----------------
extern "C" void kernel_launch(void* const* d_in, const int* in_sizes, int n_in,
                              void* d_out, int out_size) {
    const float* inp = (const float*)d_in[0];
    const float* gw  = (const float*)d_in[1];
    const float* gb  = (const float*)d_in[2];
    const float* w1  = (const float*)d_in[3];
    const float* b1  = (const float*)d_in[4];
    const float* w2  = (const float*)d_in[5];
    const float* b2  = (const float*)d_in[6];
    float* out = (float*)d_out;

    cudaFuncSetAttribute(gemm1_mma, cudaFuncAttributeMaxDynamicSharedMemorySize, SMEM_BYTES);
    cudaFuncSetAttribute(gemm2_mma, cudaFuncAttributeMaxDynamicSharedMemorySize, SMEM_BYTES);

    zero_kernel<<<1, 32>>>();
    gate_kernel<<<NTOK, 256>>>(inp, gw, gb);
    convert_x<<<(NTOK * DM / 4 + 255) / 256, 256>>>(inp);
    convert_w1_fast<<<dim3(HM / 64, DM / 64, NE), 256>>>(w1);
    convert_w2_fast<<<dim3(DM / 64, HM / 64, NE), 256>>>(w2);
    gemm1_mma<<<dim3(CAP / BM, HM / BN, NE), 256, SMEM_BYTES>>>(b1);
    gemm2_mma<<<dim3(CAP / BM, DM / BN, NE), 256, SMEM_BYTES>>>(b2);
    combine_kernel<<<(NTOK * (DM / 4) + 255) / 256, 256>>>(out);
}

// round 17
// speedup vs baseline: 1.4887x; 1.3933x over previous
#include <cuda_runtime.h>
#include <cuda_fp16.h>
#include <cstdint>
#include <math.h>

#define NE   8
#define DM   768
#define HM   3072
#define NTOK 4096
#define CAP  2048

#define BM 128
#define BN 128
#define BK 32
#define KSTRIDE 40                 // padded SMEM row stride in fp16 elems (80B)
#define TILE_B   (BM * KSTRIDE * 2)        // 10240 bytes per tile
#define STAGE_B  (3 * TILE_B)              // Ah, Bh, Bl (30720 B)
#define SMEM_BYTES (2 * STAGE_B)           // 61440 -> 2 CTAs/SM with headroom

using f16 = __half;

// ---------------- device scratch ----------------
__device__ int   g_count[NE];
__device__ int   g_rows[NE * CAP];
__device__ int   g_slot_e[NTOK * 2];
__device__ int   g_slot_p[NTOK * 2];
__device__ float g_score[NTOK * 2];

__device__ __align__(16) f16   g_xh[NTOK * DM];
__device__ __align__(16) f16   g_w1h[(size_t)NE * HM * DM];   // transposed: [e][h][d]
__device__ __align__(16) f16   g_w1l[(size_t)NE * HM * DM];
__device__ __align__(16) f16   g_w2h[(size_t)NE * DM * HM];   // transposed: [e][d][h]
__device__ __align__(16) f16   g_w2l[(size_t)NE * DM * HM];
__device__ __align__(16) f16   g_Hh[(size_t)NE * CAP * HM];
__device__ __align__(16) float g_Y[(size_t)NE * CAP * DM];

// ---------------- helpers ----------------
__device__ __forceinline__ uint32_t smem_u32(const void* p) {
    uint32_t a;
    asm("{ .reg .u64 t; cvta.to.shared.u64 t, %1; cvt.u32.u64 %0, t; }" : "=r"(a) : "l"(p));
    return a;
}
__device__ __forceinline__ void cp16(uint32_t dst, const void* src, int szbytes) {
    asm volatile("cp.async.cg.shared.global [%0], [%1], 16, %2;"
                 :: "r"(dst), "l"(src), "r"(szbytes) : "memory");
}
#define CP_COMMIT asm volatile("cp.async.commit_group;" ::: "memory")
#define CP_WAIT1  asm volatile("cp.async.wait_group 1;" ::: "memory")

#define LDSM4(r0, r1, r2, r3, addr)                                              \
    asm volatile("ldmatrix.sync.aligned.m8n8.x4.shared.b16 {%0,%1,%2,%3}, [%4];" \
                 : "=r"(r0), "=r"(r1), "=r"(r2), "=r"(r3) : "r"(addr))

__device__ __forceinline__ void mma16816(float* c,
                                         uint32_t a0, uint32_t a1, uint32_t a2, uint32_t a3,
                                         uint32_t b0, uint32_t b1) {
    asm volatile(
        "mma.sync.aligned.m16n8k16.row.col.f32.f16.f16.f32 "
        "{%0,%1,%2,%3}, {%4,%5,%6,%7}, {%8,%9}, {%0,%1,%2,%3};"
        : "+f"(c[0]), "+f"(c[1]), "+f"(c[2]), "+f"(c[3])
        : "r"(a0), "r"(a1), "r"(a2), "r"(a3), "r"(b0), "r"(b1));
}

__device__ __forceinline__ void split2(float v, f16& h, f16& l) {
    h = __float2half_rn(v);
    l = __float2half_rn(v - __half2float(h));
}
__device__ __forceinline__ uint32_t pack_hf(f16 a, f16 b) {
    unsigned short ua = *(unsigned short*)&a, ub = *(unsigned short*)&b;
    return (uint32_t)ua | ((uint32_t)ub << 16);
}
__device__ __forceinline__ float gelu_tanh(float v) {
    float u = 0.7978845608028654f * (v + 0.044715f * v * v * v);
    return 0.5f * v * (1.f + tanhf(u));
}

// one BK=32 stage of the 2-pass fp16 split MMA: acc += Ah*(Bh + Bl)
__device__ __forceinline__ void tile_compute(uint32_t As, int lane, int wm, int wn,
                                             float acc[4][4][4]) {
    const uint32_t Bhi = As + TILE_B, Blo = As + 2 * TILE_B;
#pragma unroll
    for (int ks = 0; ks < 2; ++ks) {
        uint32_t ah[16], bh[8], bl[8];
        const int arow = lane & 15, acol = ks * 16 + ((lane >> 4) << 3);
        const int brow = (lane & 7) + (((lane >> 4) & 1) << 3);
        const int bcol = ks * 16 + (((lane >> 3) & 1) << 3);
#pragma unroll
        for (int i = 0; i < 4; ++i) {
            uint32_t a = As + (uint32_t)((wm + i * 16 + arow) * KSTRIDE + acol) * 2;
            LDSM4(ah[4 * i], ah[4 * i + 1], ah[4 * i + 2], ah[4 * i + 3], a);
        }
#pragma unroll
        for (int p = 0; p < 2; ++p) {
            uint32_t a = Bhi + (uint32_t)((wn + p * 16 + brow) * KSTRIDE + bcol) * 2;
            LDSM4(bh[4 * p], bh[4 * p + 1], bh[4 * p + 2], bh[4 * p + 3], a);
        }
#pragma unroll
        for (int i = 0; i < 4; ++i)
#pragma unroll
            for (int j = 0; j < 4; ++j)
                mma16816(acc[i][j], ah[4 * i], ah[4 * i + 1], ah[4 * i + 2], ah[4 * i + 3],
                         bh[(j >> 1) * 4 + (j & 1) * 2], bh[(j >> 1) * 4 + (j & 1) * 2 + 1]);
#pragma unroll
        for (int p = 0; p < 2; ++p) {
            uint32_t a = Blo + (uint32_t)((wn + p * 16 + brow) * KSTRIDE + bcol) * 2;
            LDSM4(bl[4 * p], bl[4 * p + 1], bl[4 * p + 2], bl[4 * p + 3], a);
        }
#pragma unroll
        for (int i = 0; i < 4; ++i)
#pragma unroll
            for (int j = 0; j < 4; ++j)
                mma16816(acc[i][j], ah[4 * i], ah[4 * i + 1], ah[4 * i + 2], ah[4 * i + 3],
                         bl[(j >> 1) * 4 + (j & 1) * 2], bl[(j >> 1) * 4 + (j & 1) * 2 + 1]);
    }
}

// ---------------- control kernels ----------------
__global__ void zero_kernel() {
    if (threadIdx.x < NE) g_count[threadIdx.x] = 0;
}

__global__ void gate_kernel(const float* __restrict__ inp,
                            const float* __restrict__ gw,
                            const float* __restrict__ gb) {
    int n = blockIdx.x, tid = threadIdx.x;
    float acc[NE];
#pragma unroll
    for (int e = 0; e < NE; e++) acc[e] = 0.f;
    const float* x = inp + (size_t)n * DM;
    for (int d = tid; d < DM; d += 256) {
        float xv = x[d];
#pragma unroll
        for (int e = 0; e < NE; e++) acc[e] += xv * gw[d * NE + e];
    }
#pragma unroll
    for (int e = 0; e < NE; e++)
#pragma unroll
        for (int off = 16; off > 0; off >>= 1)
            acc[e] += __shfl_down_sync(0xffffffffu, acc[e], off);
    __shared__ float sred[8][NE];
    int warp = tid >> 5, lane = tid & 31;
    if (lane == 0)
#pragma unroll
        for (int e = 0; e < NE; e++) sred[warp][e] = acc[e];
    __syncthreads();
    if (tid == 0) {
        float logits[NE];
#pragma unroll
        for (int e = 0; e < NE; e++) {
            float s = gb[e];
#pragma unroll
            for (int w = 0; w < 8; w++) s += sred[w][e];
            logits[e] = s;
        }
        int i0 = 0;
#pragma unroll
        for (int e = 1; e < NE; e++) if (logits[e] > logits[i0]) i0 = e;
        int i1 = -1;
#pragma unroll
        for (int e = 0; e < NE; e++) {
            if (e == i0) continue;
            if (i1 < 0 || logits[e] > logits[i1]) i1 = e;
        }
        float v0 = logits[i0], v1 = logits[i1];
        float e1 = expf(v1 - v0);
        float inv = 1.f / (1.f + e1);
        int p0 = atomicAdd(&g_count[i0], 1);
        int p1 = atomicAdd(&g_count[i1], 1);
        if (p0 < CAP) g_rows[i0 * CAP + p0] = n; else p0 = -1;
        if (p1 < CAP) g_rows[i1 * CAP + p1] = n; else p1 = -1;
        g_slot_e[n * 2 + 0] = i0; g_slot_p[n * 2 + 0] = p0; g_score[n * 2 + 0] = inv;
        g_slot_e[n * 2 + 1] = i1; g_slot_p[n * 2 + 1] = p1; g_score[n * 2 + 1] = e1 * inv;
    }
}

// ---------------- streaming fp32 -> fp16 (X: hi only, no transpose) ----------------
__global__ void convert_x(const float* __restrict__ x) {
    int i4 = blockIdx.x * blockDim.x + threadIdx.x;
    if (i4 >= NTOK * DM / 4) return;
    float4 v = ((const float4*)x)[i4];
    f16 h0 = __float2half_rn(v.x), h1 = __float2half_rn(v.y);
    f16 h2 = __float2half_rn(v.z), h3 = __float2half_rn(v.w);
    ((uint2*)g_xh)[i4] = make_uint2(pack_hf(h0, h1), pack_hf(h2, h3));
}

// ---------------- fast transpose + fp16 hi/lo split: src [E][K][N] -> dst [E][N][K] ----
__device__ __forceinline__ void transpose_split_tile(const float* __restrict__ src,
                                                     f16* __restrict__ dh,
                                                     f16* __restrict__ dl,
                                                     int K, int N) {
    __shared__ float s[64][65];
    const int e = blockIdx.z, k0 = blockIdx.y * 64, n0 = blockIdx.x * 64;
    const int tid = threadIdx.x;
    const float* sp = src + ((size_t)e * K + k0) * N + n0;
#pragma unroll
    for (int l = 0; l < 4; ++l) {
        int idx = tid + l * 256;
        int r = idx >> 4, c = (idx & 15) * 4;
        float4 v = *(const float4*)(sp + (size_t)r * N + c);
        s[r][c + 0] = v.x; s[r][c + 1] = v.y; s[r][c + 2] = v.z; s[r][c + 3] = v.w;
    }
    __syncthreads();
    f16* dhp = dh + ((size_t)e * N + n0) * K + k0;
    f16* dlp = dl + ((size_t)e * N + n0) * K + k0;
#pragma unroll
    for (int l = 0; l < 2; ++l) {
        int idx = tid + l * 256;
        int r = idx >> 3, c8 = (idx & 7) * 8;      // r = n-row, c8 = k-offset
        f16 h[8], lo[8];
#pragma unroll
        for (int q = 0; q < 8; ++q) split2(s[c8 + q][r], h[q], lo[q]);
        uint4 hv = make_uint4(pack_hf(h[0], h[1]), pack_hf(h[2], h[3]),
                              pack_hf(h[4], h[5]), pack_hf(h[6], h[7]));
        uint4 lv = make_uint4(pack_hf(lo[0], lo[1]), pack_hf(lo[2], lo[3]),
                              pack_hf(lo[4], lo[5]), pack_hf(lo[6], lo[7]));
        *(uint4*)(dhp + (size_t)r * K + c8) = hv;
        *(uint4*)(dlp + (size_t)r * K + c8) = lv;
    }
}
__global__ void __launch_bounds__(256) convert_w1_fast(const float* __restrict__ w) {
    transpose_split_tile(w, g_w1h, g_w1l, DM, HM);   // [e][DM][HM] -> [e][HM][DM]
}
__global__ void __launch_bounds__(256) convert_w2_fast(const float* __restrict__ w) {
    transpose_split_tile(w, g_w2h, g_w2l, HM, DM);   // [e][HM][DM] -> [e][DM][HM]
}

// ---------------- GEMM1 ----------------
__global__ void __launch_bounds__(256, 2) gemm1_mma(const float* __restrict__ b1) {
    extern __shared__ char smem[];
    const int tid = threadIdx.x, wid = tid >> 5, lane = tid & 31;
    const int e = blockIdx.z, m0 = blockIdx.x * BM, n0 = blockIdx.y * BN;
    const int cnt = min(g_count[e], CAP);
    if (m0 >= cnt) return;

    __shared__ int rowTok[BM];
    if (tid < BM) rowTok[tid] = (m0 + tid < cnt) ? g_rows[e * CAP + m0 + tid] : -1;
    __syncthreads();

    const uint32_t sbase = smem_u32(smem);
    const int wm = (wid & 1) * 64, wn = (wid >> 1) * 32;

    float acc[4][4][4];
#pragma unroll
    for (int i = 0; i < 4; ++i)
#pragma unroll
        for (int j = 0; j < 4; ++j)
#pragma unroll
            for (int q = 0; q < 4; ++q) acc[i][j][q] = 0.f;

    auto load_stage = [&](int stage, int k0) {
        uint32_t st = sbase + stage * STAGE_B;
#pragma unroll
        for (int l = 0; l < 2; ++l) {
            int idx = tid + l * 256;
            int r = idx >> 2, c = idx & 3;
            uint32_t doff = (uint32_t)(r * KSTRIDE + c * 8) * 2;
            int tok = rowTok[r];
            size_t aoff = (size_t)max(tok, 0) * DM + k0 + c * 8;
            int sz = tok >= 0 ? 16 : 0;
            cp16(st + doff, g_xh + aoff, sz);
            size_t brow = ((size_t)e * HM + n0 + r) * DM + k0 + c * 8;
            cp16(st + TILE_B + doff, g_w1h + brow, 16);
            cp16(st + 2 * TILE_B + doff, g_w1l + brow, 16);
        }
    };

    load_stage(0, 0);
    CP_COMMIT;
    const int KT = DM / BK;
#pragma unroll 1
    for (int kt = 0; kt < KT; ++kt) {
        if (kt + 1 < KT) load_stage((kt + 1) & 1, (kt + 1) * BK);
        CP_COMMIT;
        CP_WAIT1;
        __syncthreads();
        tile_compute(sbase + (kt & 1) * STAGE_B, lane, wm, wn, acc);
        __syncthreads();
    }

    const float* b1e = b1 + (size_t)e * HM;
#pragma unroll
    for (int i = 0; i < 4; ++i) {
        int rbase = m0 + wm + i * 16 + (lane >> 2);
#pragma unroll
        for (int h = 0; h < 2; ++h) {
            int r = rbase + h * 8;
            if (r >= cnt) continue;
            size_t rowoff = ((size_t)e * CAP + r) * HM;
#pragma unroll
            for (int j = 0; j < 4; ++j) {
                int col = n0 + wn + j * 8 + (lane & 3) * 2;
                float v0 = gelu_tanh(acc[i][j][h * 2 + 0] + b1e[col]);
                float v1 = gelu_tanh(acc[i][j][h * 2 + 1] + b1e[col + 1]);
                *(uint32_t*)(g_Hh + rowoff + col) =
                    pack_hf(__float2half_rn(v0), __float2half_rn(v1));
            }
        }
    }
}

// ---------------- GEMM2 ----------------
__global__ void __launch_bounds__(256, 2) gemm2_mma(const float* __restrict__ b2) {
    extern __shared__ char smem[];
    const int tid = threadIdx.x, wid = tid >> 5, lane = tid & 31;
    const int e = blockIdx.z, m0 = blockIdx.x * BM, n0 = blockIdx.y * BN;
    const int cnt = min(g_count[e], CAP);
    if (m0 >= cnt) return;

    const uint32_t sbase = smem_u32(smem);
    const int wm = (wid & 1) * 64, wn = (wid >> 1) * 32;

    float acc[4][4][4];
#pragma unroll
    for (int i = 0; i < 4; ++i)
#pragma unroll
        for (int j = 0; j < 4; ++j)
#pragma unroll
            for (int q = 0; q < 4; ++q) acc[i][j][q] = 0.f;

    auto load_stage = [&](int stage, int k0) {
        uint32_t st = sbase + stage * STAGE_B;
#pragma unroll
        for (int l = 0; l < 2; ++l) {
            int idx = tid + l * 256;
            int r = idx >> 2, c = idx & 3;
            uint32_t doff = (uint32_t)(r * KSTRIDE + c * 8) * 2;
            int mrow = m0 + r;
            int sz = mrow < cnt ? 16 : 0;
            size_t aoff = ((size_t)e * CAP + mrow) * HM + k0 + c * 8;
            cp16(st + doff, g_Hh + aoff, sz);
            size_t brow = ((size_t)e * DM + n0 + r) * HM + k0 + c * 8;
            cp16(st + TILE_B + doff, g_w2h + brow, 16);
            cp16(st + 2 * TILE_B + doff, g_w2l + brow, 16);
        }
    };

    load_stage(0, 0);
    CP_COMMIT;
    const int KT = HM / BK;
#pragma unroll 1
    for (int kt = 0; kt < KT; ++kt) {
        if (kt + 1 < KT) load_stage((kt + 1) & 1, (kt + 1) * BK);
        CP_COMMIT;
        CP_WAIT1;
        __syncthreads();
        tile_compute(sbase + (kt & 1) * STAGE_B, lane, wm, wn, acc);
        __syncthreads();
    }

    const float* b2e = b2 + (size_t)e * DM;
#pragma unroll
    for (int i = 0; i < 4; ++i) {
        int rbase = m0 + wm + i * 16 + (lane >> 2);
#pragma unroll
        for (int h = 0; h < 2; ++h) {
            int r = rbase + h * 8;
            if (r >= cnt) continue;
            size_t rowoff = ((size_t)e * CAP + r) * DM;
#pragma unroll
            for (int j = 0; j < 4; ++j) {
                int col = n0 + wn + j * 8 + (lane & 3) * 2;
                float2 o;
                o.x = acc[i][j][h * 2 + 0] + b2e[col];
                o.y = acc[i][j][h * 2 + 1] + b2e[col + 1];
                *(float2*)(g_Y + rowoff + col) = o;
            }
        }
    }
}

// ---------------- combine ----------------
__global__ void combine_kernel(float* __restrict__ out) {
    int idx = blockIdx.x * blockDim.x + threadIdx.x;
    if (idx >= NTOK * (DM / 4)) return;
    int n = idx / (DM / 4), d4 = idx % (DM / 4);
    int   e0 = g_slot_e[n * 2 + 0], p0 = g_slot_p[n * 2 + 0];
    int   e1 = g_slot_e[n * 2 + 1], p1 = g_slot_p[n * 2 + 1];
    float s0 = g_score[n * 2 + 0],  s1 = g_score[n * 2 + 1];
    float4 r = make_float4(0.f, 0.f, 0.f, 0.f);
    if (p0 >= 0) {
        float4 y = *(const float4*)&g_Y[((size_t)e0 * CAP + p0) * DM + d4 * 4];
        r.x += s0 * y.x; r.y += s0 * y.y; r.z += s0 * y.z; r.w += s0 * y.w;
    }
    if (p1 >= 0) {
        float4 y = *(const float4*)&g_Y[((size_t)e1 * CAP + p1) * DM + d4 * 4];
        r.x += s1 * y.x; r.y += s1 * y.y; r.z += s1 * y.z; r.w += s1 * y.w;
    }
    *(float4*)&out[(size_t)n * DM + d4 * 4] = r;
}

// ---------------- launch ----------------
extern "C" void kernel_launch(void* const* d_in, const int* in_sizes, int n_in,
                              void* d_out, int out_size) {
    const float* inp = (const float*)d_in[0];
    const float* gw  = (const float*)d_in[1];
    const float* gb  = (const float*)d_in[2];
    const float* w1  = (const float*)d_in[3];
    const float* b1  = (const float*)d_in[4];
    const float* w2  = (const float*)d_in[5];
    const float* b2  = (const float*)d_in[6];
    float* out = (float*)d_out;

    cudaFuncSetAttribute(gemm1_mma, cudaFuncAttributeMaxDynamicSharedMemorySize, SMEM_BYTES);
    cudaFuncSetAttribute(gemm2_mma, cudaFuncAttributeMaxDynamicSharedMemorySize, SMEM_BYTES);

    zero_kernel<<<1, 32>>>();
    gate_kernel<<<NTOK, 256>>>(inp, gw, gb);
    convert_x<<<(NTOK * DM / 4 + 255) / 256, 256>>>(inp);
    convert_w1_fast<<<dim3(HM / 64, DM / 64, NE), 256>>>(w1);
    convert_w2_fast<<<dim3(DM / 64, HM / 64, NE), 256>>>(w2);
    gemm1_mma<<<dim3(CAP / BM, HM / BN, NE), 256, SMEM_BYTES>>>(b1);
    gemm2_mma<<<dim3(CAP / BM, DM / BN, NE), 256, SMEM_BYTES>>>(b2);
    combine_kernel<<<(NTOK * (DM / 4) + 255) / 256, 256>>>(out);
}